// round 2
// baseline (speedup 1.0000x reference)
#include <cuda_runtime.h>
#include <math.h>

// Problem constants
#define BB   2
#define LL   1024
#define DD   1024
#define EDIM 2048
#define NS   16
#define DCV  4
#define DTR  64
#define VV   32000
#define RTOT (BB*LL)   // 2048 rows

// ---------------- scratch (device globals; no allocs allowed) ----------------
__device__ float g_x[RTOT*DD];          // embed out
__device__ float g_xz[RTOT*2*EDIM];     // in_proj out (xm | z)
__device__ float g_xm[RTOT*EDIM];       // conv+silu out
__device__ float g_dbl[RTOT*(DTR+2*NS)];// x_proj out [delta | B | C]
__device__ float g_delta[RTOT*EDIM];    // softplus(dt_proj)
__device__ float g_y[RTOT*EDIM];        // scan out (incl. *silu(z))
__device__ float g_m0[RTOT*DD];         // mamba out
__device__ float g_ln0[RTOT*DD];
__device__ float g_qkv[RTOT*3*DD];
__device__ float g_scores[BB*LL*LL];
__device__ float g_attn[RTOT*DD];
__device__ float g_ln1[RTOT*DD];

// ---------------- embed gather ----------------
__global__ void embed_kernel(const int* __restrict__ tokens,
                             const float* __restrict__ ew,
                             float* __restrict__ out) {
    int row = blockIdx.x;
    int tok = tokens[row];
    const float4* src = (const float4*)(ew + (long long)tok * DD);
    float4* dst = (float4*)(out + (long long)row * DD);
    dst[threadIdx.x] = src[threadIdx.x];
}

// ---------------- generic SGEMM: C[M,N] = A[M,K] @ B (+bias, +act) ----------------
// TRANSB=0: B is [K,N] row-major (ldb); TRANSB=1: B is [N,K] row-major (ldb), C=A*B^T
// Assumes M % 128 == 0, K % 8 == 0. N-edge handled (guards).
// act: 0=none, 1=softplus
template<int TRANSB>
__global__ void sgemm_kernel(const float* __restrict__ A, const float* __restrict__ B,
                             float* __restrict__ C,
                             int M, int N, int K, int lda, int ldb, int ldc,
                             long long sA, long long sB, long long sC,
                             const float* __restrict__ bias, int act) {
    __shared__ __align__(16) float As[8][128];
    __shared__ __align__(16) float Bs[8][128];

    int bz = blockIdx.z;
    A += (long long)bz * sA;
    B += (long long)bz * sB;
    C += (long long)bz * sC;

    int n0 = blockIdx.x * 128;
    int m0 = blockIdx.y * 128;
    int tid = threadIdx.x;
    int tx = tid & 15;      // 0..15
    int ty = tid >> 4;      // 0..15
    bool fullN = (n0 + 128 <= N);

    float acc[8][8];
#pragma unroll
    for (int i = 0; i < 8; i++)
#pragma unroll
        for (int j = 0; j < 8; j++) acc[i][j] = 0.f;

    int aRow = tid >> 1;          // 0..127
    int aCol = (tid & 1) * 4;     // 0 or 4

    for (int k0 = 0; k0 < K; k0 += 8) {
        // stage loads
        float4 av = *(const float4*)(A + (long long)(m0 + aRow) * lda + k0 + aCol);
        float4 bv;
        if (TRANSB) {
            int bN = tid >> 1;         // 0..127
            int bK = (tid & 1) * 4;
            if (fullN || (n0 + bN) < N)
                bv = *(const float4*)(B + (long long)(n0 + bN) * ldb + k0 + bK);
            else
                bv = make_float4(0.f, 0.f, 0.f, 0.f);
        } else {
            int bRow = tid >> 5;       // 0..7
            int bCol = (tid & 31) * 4; // 0..124
            const float* bp = B + (long long)(k0 + bRow) * ldb + n0 + bCol;
            if (fullN) {
                bv = *(const float4*)bp;
            } else {
                bv.x = (n0 + bCol + 0 < N) ? bp[0] : 0.f;
                bv.y = (n0 + bCol + 1 < N) ? bp[1] : 0.f;
                bv.z = (n0 + bCol + 2 < N) ? bp[2] : 0.f;
                bv.w = (n0 + bCol + 3 < N) ? bp[3] : 0.f;
            }
        }
        __syncthreads();  // previous tile fully consumed
        As[aCol + 0][aRow] = av.x;
        As[aCol + 1][aRow] = av.y;
        As[aCol + 2][aRow] = av.z;
        As[aCol + 3][aRow] = av.w;
        if (TRANSB) {
            int bN = tid >> 1;
            int bK = (tid & 1) * 4;
            Bs[bK + 0][bN] = bv.x;
            Bs[bK + 1][bN] = bv.y;
            Bs[bK + 2][bN] = bv.z;
            Bs[bK + 3][bN] = bv.w;
        } else {
            int bRow = tid >> 5;
            int bCol = (tid & 31) * 4;
            *(float4*)&Bs[bRow][bCol] = bv;
        }
        __syncthreads();

#pragma unroll
        for (int kk = 0; kk < 8; kk++) {
            float ra[8], rb[8];
            *(float4*)&ra[0] = *(const float4*)&As[kk][ty * 4];
            *(float4*)&ra[4] = *(const float4*)&As[kk][64 + ty * 4];
            *(float4*)&rb[0] = *(const float4*)&Bs[kk][tx * 4];
            *(float4*)&rb[4] = *(const float4*)&Bs[kk][64 + tx * 4];
#pragma unroll
            for (int i = 0; i < 8; i++)
#pragma unroll
                for (int j = 0; j < 8; j++)
                    acc[i][j] += ra[i] * rb[j];
        }
    }

    // epilogue
#pragma unroll
    for (int i = 0; i < 8; i++) {
        int r = m0 + ((i < 4) ? (ty * 4 + i) : (64 + ty * 4 + i - 4));
#pragma unroll
        for (int j = 0; j < 8; j++) {
            int c = n0 + ((j < 4) ? (tx * 4 + j) : (64 + tx * 4 + j - 4));
            if (c < N) {
                float v = acc[i][j];
                if (bias) v += bias[c];
                if (act == 1) v = (v > 20.f) ? v : log1pf(__expf(v));
                C[(long long)r * ldc + c] = v;
            }
        }
    }
}

// ---------------- causal depthwise conv (DCV=4) + bias + SiLU ----------------
__global__ void conv_silu_kernel(const float* __restrict__ xz,
                                 const float* __restrict__ cw,
                                 const float* __restrict__ cb,
                                 float* __restrict__ out) {
    int idx = blockIdx.x * blockDim.x + threadIdx.x;
    if (idx >= RTOT * EDIM) return;
    int e = idx % EDIM;
    int r = idx / EDIM;
    int l = r % LL;
    int b = r / LL;
    float acc = cb[e];
#pragma unroll
    for (int t = 0; t < DCV; t++) {
        int ll = l - (DCV - 1) + t;
        if (ll >= 0)
            acc += cw[e * DCV + t] * xz[(long long)(b * LL + ll) * (2 * EDIM) + e];
    }
    out[idx] = acc / (1.f + __expf(-acc));  // silu
}

// ---------------- selective scan: thread per (b, ed), h[16] in regs ----------------
__global__ void scan_kernel(const float* __restrict__ dbl,
                            const float* __restrict__ delta,
                            const float* __restrict__ xm,
                            const float* __restrict__ xz,
                            const float* __restrict__ A_log,
                            const float* __restrict__ Dp,
                            float* __restrict__ y) {
    int b = blockIdx.y;
    int ed = blockIdx.x * blockDim.x + threadIdx.x;

    float Av[NS];
#pragma unroll
    for (int n = 0; n < NS; n++) Av[n] = -__expf(A_log[ed * NS + n]);
    float h[NS];
#pragma unroll
    for (int n = 0; n < NS; n++) h[n] = 0.f;
    float dp = Dp[ed];

    __shared__ float sBC[32][32];  // 32 timesteps x (B[16] | C[16])

    for (int l0 = 0; l0 < LL; l0 += 32) {
        __syncthreads();
        for (int u = threadIdx.x; u < 32 * 32; u += blockDim.x) {
            int i = u >> 5, j = u & 31;
            sBC[i][j] = dbl[(long long)(b * LL + l0 + i) * (DTR + 2 * NS) + DTR + j];
        }
        __syncthreads();
        for (int i = 0; i < 32; i++) {
            long long row = (long long)b * LL + l0 + i;
            float dlt = delta[row * EDIM + ed];
            float xmv = xm[row * EDIM + ed];
            float zv  = xz[row * (2 * EDIM) + EDIM + ed];
            float dx = dlt * xmv;
            float acc = 0.f;
#pragma unroll
            for (int n = 0; n < NS; n++) {
                float dA = __expf(dlt * Av[n]);
                h[n] = dA * h[n] + dx * sBC[i][n];
                acc += h[n] * sBC[i][NS + n];
            }
            float yv = acc + xmv * dp;
            yv *= zv / (1.f + __expf(-zv));   // * silu(z)
            y[row * EDIM + ed] = yv;
        }
    }
}

// ---------------- layernorm over D=1024 ----------------
__global__ void layernorm_kernel(const float* __restrict__ x,
                                 const float* __restrict__ w,
                                 const float* __restrict__ b,
                                 float* __restrict__ out) {
    int row = blockIdx.x;
    int tid = threadIdx.x;
    const float4 v = ((const float4*)(x + (long long)row * DD))[tid];
    float s  = v.x + v.y + v.z + v.w;
    float sq = v.x * v.x + v.y * v.y + v.z * v.z + v.w * v.w;

    __shared__ float ss[256], s2[256];
    ss[tid] = s; s2[tid] = sq;
    __syncthreads();
    for (int st = 128; st > 0; st >>= 1) {
        if (tid < st) { ss[tid] += ss[tid + st]; s2[tid] += s2[tid + st]; }
        __syncthreads();
    }
    float mean = ss[0] * (1.f / DD);
    float var  = s2[0] * (1.f / DD) - mean * mean;
    float inv  = rsqrtf(var + 1e-5f);

    float4 wv = ((const float4*)w)[tid];
    float4 bv = ((const float4*)b)[tid];
    float4 o;
    o.x = (v.x - mean) * inv * wv.x + bv.x;
    o.y = (v.y - mean) * inv * wv.y + bv.y;
    o.z = (v.z - mean) * inv * wv.z + bv.z;
    o.w = (v.w - mean) * inv * wv.w + bv.w;
    ((float4*)(out + (long long)row * DD))[tid] = o;
}

// ---------------- causal masked softmax over score rows ----------------
__global__ void softmax_causal_kernel(float* __restrict__ s) {
    int row = blockIdx.x;     // b*LL + q
    int q = row % LL;
    int tid = threadIdx.x;
    float* sr = s + (long long)row * LL;
    const float scale = 0.03125f;  // 1/sqrt(1024)

    __shared__ float sh[256];
    float mx = -1e30f;
    for (int k = tid; k <= q; k += 256) mx = fmaxf(mx, sr[k] * scale);
    sh[tid] = mx; __syncthreads();
    for (int st = 128; st > 0; st >>= 1) {
        if (tid < st) sh[tid] = fmaxf(sh[tid], sh[tid + st]);
        __syncthreads();
    }
    mx = sh[0];
    __syncthreads();

    float sum = 0.f;
    for (int k = tid; k <= q; k += 256) {
        float e = __expf(sr[k] * scale - mx);
        sr[k] = e;
        sum += e;
    }
    sh[tid] = sum; __syncthreads();
    for (int st = 128; st > 0; st >>= 1) {
        if (tid < st) sh[tid] += sh[tid + st];
        __syncthreads();
    }
    float inv = 1.f / sh[0];

    for (int k = tid; k < LL; k += 256) sr[k] = (k <= q) ? sr[k] * inv : 0.f;
}

// ---------------- launch ----------------
extern "C" void kernel_launch(void* const* d_in, const int* in_sizes, int n_in,
                              void* d_out, int out_size) {
    const int*   tokens     = (const int*)  d_in[0];
    const float* embed_w    = (const float*)d_in[1];
    const float* in_proj_w  = (const float*)d_in[2];
    const float* conv_w     = (const float*)d_in[3];
    const float* conv_b     = (const float*)d_in[4];
    const float* x_proj_w   = (const float*)d_in[5];
    const float* dt_proj_w  = (const float*)d_in[6];
    const float* dt_proj_b  = (const float*)d_in[7];
    const float* A_log      = (const float*)d_in[8];
    const float* D_p        = (const float*)d_in[9];
    const float* out_proj_w = (const float*)d_in[10];
    const float* ln0_w      = (const float*)d_in[11];
    const float* ln0_b      = (const float*)d_in[12];
    const float* ln1_w      = (const float*)d_in[13];
    const float* ln1_b      = (const float*)d_in[14];
    const float* c_attn_w   = (const float*)d_in[15];
    const float* c_attn_b   = (const float*)d_in[16];
    const float* head_w     = (const float*)d_in[17];
    const float* head_b     = (const float*)d_in[18];
    float* out = (float*)d_out;

    float *px, *pxz, *pxm, *pdbl, *pdelta, *py, *pm0, *pln0, *pqkv, *pscores, *pattn, *pln1;
    cudaGetSymbolAddress((void**)&px,      g_x);
    cudaGetSymbolAddress((void**)&pxz,     g_xz);
    cudaGetSymbolAddress((void**)&pxm,     g_xm);
    cudaGetSymbolAddress((void**)&pdbl,    g_dbl);
    cudaGetSymbolAddress((void**)&pdelta,  g_delta);
    cudaGetSymbolAddress((void**)&py,      g_y);
    cudaGetSymbolAddress((void**)&pm0,     g_m0);
    cudaGetSymbolAddress((void**)&pln0,    g_ln0);
    cudaGetSymbolAddress((void**)&pqkv,    g_qkv);
    cudaGetSymbolAddress((void**)&pscores, g_scores);
    cudaGetSymbolAddress((void**)&pattn,   g_attn);
    cudaGetSymbolAddress((void**)&pln1,    g_ln1);

    // 1) embed
    embed_kernel<<<RTOT, 256>>>(tokens, embed_w, px);

    // 2) in_proj: [2048,1024] @ [1024,4096] -> g_xz
    {
        dim3 g(2 * EDIM / 128, RTOT / 128, 1);
        sgemm_kernel<0><<<g, 256>>>(px, in_proj_w, pxz, RTOT, 2 * EDIM, DD,
                                    DD, 2 * EDIM, 2 * EDIM, 0, 0, 0, nullptr, 0);
    }

    // 3) causal depthwise conv + SiLU -> g_xm
    conv_silu_kernel<<<(RTOT * EDIM + 255) / 256, 256>>>(pxz, conv_w, conv_b, pxm);

    // 4) x_proj: [2048,2048] @ [2048,96] -> g_dbl (N=96, guarded)
    {
        dim3 g(1, RTOT / 128, 1);
        sgemm_kernel<0><<<g, 256>>>(pxm, x_proj_w, pdbl, RTOT, DTR + 2 * NS, EDIM,
                                    EDIM, DTR + 2 * NS, DTR + 2 * NS, 0, 0, 0, nullptr, 0);
    }

    // 5) dt_proj + bias + softplus: [2048,64] @ [64,2048] -> g_delta
    {
        dim3 g(EDIM / 128, RTOT / 128, 1);
        sgemm_kernel<0><<<g, 256>>>(pdbl, dt_proj_w, pdelta, RTOT, EDIM, DTR,
                                    DTR + 2 * NS, EDIM, EDIM, 0, 0, 0, dt_proj_b, 1);
    }

    // 6) selective scan (+ xm*Dp, * silu(z)) -> g_y
    {
        dim3 g(EDIM / 256, BB);
        scan_kernel<<<g, 256>>>(pdbl, pdelta, pxm, pxz, A_log, D_p, py);
    }

    // 7) out_proj: [2048,2048] @ [2048,1024] -> g_m0
    {
        dim3 g(DD / 128, RTOT / 128, 1);
        sgemm_kernel<0><<<g, 256>>>(py, out_proj_w, pm0, RTOT, DD, EDIM,
                                    EDIM, DD, DD, 0, 0, 0, nullptr, 0);
    }

    // 8) layernorm 0
    layernorm_kernel<<<RTOT, 256>>>(pm0, ln0_w, ln0_b, pln0);

    // 9) c_attn + bias: [2048,1024] @ [1024,3072] -> g_qkv
    {
        dim3 g(3 * DD / 128, RTOT / 128, 1);
        sgemm_kernel<0><<<g, 256>>>(pln0, c_attn_w, pqkv, RTOT, 3 * DD, DD,
                                    DD, 3 * DD, 3 * DD, 0, 0, 0, c_attn_b, 0);
    }

    // 10) scores = q @ k^T per batch (NT), batched over z
    {
        dim3 g(LL / 128, LL / 128, BB);
        sgemm_kernel<1><<<g, 256>>>(pqkv, pqkv + DD, pscores, LL, LL, DD,
                                    3 * DD, 3 * DD, LL,
                                    (long long)LL * 3 * DD, (long long)LL * 3 * DD,
                                    (long long)LL * LL, nullptr, 0);
    }

    // 11) causal softmax (applies 1/sqrt(D) scale)
    softmax_causal_kernel<<<BB * LL, 256>>>(pscores);

    // 12) attn @ v per batch (NN), batched over z
    {
        dim3 g(LL / 128, LL / 128, BB);
        sgemm_kernel<0><<<g, 256>>>(pscores, pqkv + 2 * DD, pattn, LL, DD, LL,
                                    LL, 3 * DD, DD,
                                    (long long)LL * LL, (long long)LL * 3 * DD,
                                    (long long)LL * DD, nullptr, 0);
    }

    // 13) layernorm 1
    layernorm_kernel<<<RTOT, 256>>>(pattn, ln1_w, ln1_b, pln1);

    // 14) head + bias: [2048,1024] @ [1024,32000] -> out
    {
        dim3 g(VV / 128, RTOT / 128, 1);
        sgemm_kernel<0><<<g, 256>>>(pln1, head_w, out, RTOT, VV, DD,
                                    DD, VV, VV, 0, 0, 0, head_b, 0);
    }
}

// round 5
// speedup vs baseline: 1.9377x; 1.9377x over previous
#include <cuda_runtime.h>
#include <cuda_bf16.h>
#include <math.h>
#include <stdint.h>

// ---------------- problem constants ----------------
#define BB   2
#define LL   1024
#define DD   1024
#define EDIM 2048
#define NS   16
#define DCV  4
#define DTR  64
#define VV   32000
#define RTOT (BB*LL)
#define XW   128        // x_proj output width padded 96 -> 128

// ---------------- fp32 scratch ----------------
__device__ float g_x[RTOT*DD];
__device__ float g_xz[RTOT*2*EDIM];
__device__ float g_xm[RTOT*EDIM];
__device__ float g_dbl[RTOT*XW];        // [delta(64) | B(16) | C(16) | pad(32)]
__device__ float g_delta[RTOT*EDIM];
__device__ float g_y[RTOT*EDIM];
__device__ float g_m0[RTOT*DD];
__device__ float g_ln0[RTOT*DD];
__device__ float g_qkv[RTOT*3*DD];
__device__ float g_scores[BB*LL*LL];
__device__ float g_attn[RTOT*DD];
__device__ float g_ln1[RTOT*DD];

// ---------------- bf16 hi/lo split buffers ----------------
#define AL __align__(256)
__device__ AL __nv_bfloat16 g_xa_h[RTOT*DD],   g_xa_l[RTOT*DD];
__device__ AL __nv_bfloat16 g_xmb_h[RTOT*EDIM],g_xmb_l[RTOT*EDIM];
__device__ AL __nv_bfloat16 g_da_h[RTOT*DTR],  g_da_l[RTOT*DTR];
__device__ AL __nv_bfloat16 g_yb_h[RTOT*EDIM], g_yb_l[RTOT*EDIM];
__device__ AL __nv_bfloat16 g_l0_h[RTOT*DD],   g_l0_l[RTOT*DD];
__device__ AL __nv_bfloat16 g_qk_h[RTOT*3*DD], g_qk_l[RTOT*3*DD];
__device__ AL __nv_bfloat16 g_pb_h[BB*LL*LL],  g_pb_l[BB*LL*LL];
__device__ AL __nv_bfloat16 g_l1_h[RTOT*DD],   g_l1_l[RTOT*DD];
// weights transposed to [N, K]
__device__ AL __nv_bfloat16 g_wi_h[2*EDIM*DD], g_wi_l[2*EDIM*DD];   // in_proj^T  [4096,1024]
__device__ AL __nv_bfloat16 g_wx_h[XW*EDIM],   g_wx_l[XW*EDIM];     // x_proj^T   [128,2048]
__device__ AL __nv_bfloat16 g_wd_h[EDIM*DTR],  g_wd_l[EDIM*DTR];    // dt_proj^T  [2048,64]
__device__ AL __nv_bfloat16 g_wo_h[DD*EDIM],   g_wo_l[DD*EDIM];     // out_proj^T [1024,2048]
__device__ AL __nv_bfloat16 g_wc_h[3*DD*DD],   g_wc_l[3*DD*DD];     // c_attn^T   [3072,1024]
__device__ AL __nv_bfloat16 g_vt_h[BB*DD*LL],  g_vt_l[BB*DD*LL];    // V^T per b  [1024,1024]
__device__ AL __nv_bfloat16 g_wh_h[VV*DD],     g_wh_l[VV*DD];       // head^T     [32000,1024]

// ---------------- mma helpers (sm_80+ path; sm_100-safe) ----------------
__device__ __forceinline__ uint32_t smem_u32(const void* p) {
    uint32_t a;
    asm("{ .reg .u64 t; cvta.to.shared.u64 t, %1; cvt.u32.u64 %0, t; }" : "=r"(a) : "l"(p));
    return a;
}
__device__ __forceinline__ void ldsm4(uint32_t* r, uint32_t addr) {
    asm volatile("ldmatrix.sync.aligned.m8n8.x4.shared.b16 {%0,%1,%2,%3}, [%4];"
        : "=r"(r[0]), "=r"(r[1]), "=r"(r[2]), "=r"(r[3]) : "r"(addr));
}
__device__ __forceinline__ void mma16816(float* c, const uint32_t* a, const uint32_t* b) {
    asm volatile("mma.sync.aligned.m16n8k16.row.col.f32.bf16.bf16.f32 "
        "{%0,%1,%2,%3}, {%4,%5,%6,%7}, {%8,%9}, {%0,%1,%2,%3};"
        : "+f"(c[0]), "+f"(c[1]), "+f"(c[2]), "+f"(c[3])
        : "r"(a[0]), "r"(a[1]), "r"(a[2]), "r"(a[3]), "r"(b[0]), "r"(b[1]));
}
__device__ __forceinline__ void cpasync16(uint32_t dst, const void* src) {
    asm volatile("cp.async.cg.shared.global [%0], [%1], 16;" :: "r"(dst), "l"(src));
}
#define CP_COMMIT() asm volatile("cp.async.commit_group;" ::: "memory")
#define CP_WAIT1()  asm volatile("cp.async.wait_group 1;" ::: "memory")
#define CP_WAIT0()  asm volatile("cp.async.wait_group 0;" ::: "memory")

// smem tile: 128 rows x 32 bf16 (64B/row), swizzle: chunk ^= (row>>1)&3
__device__ __forceinline__ uint32_t sw_off(int row, int chunk) {
    return (uint32_t)(row * 64 + ((chunk ^ ((row >> 1) & 3)) << 4));
}

// ---------------- tensor GEMM: C[M,N] = (Ahi+Alo)(Bhi+Blo)^T (bf16 x3 passes) ----------------
// A row-major [M,K] (lda), B row-major [N,K] (ldb). M,N mult of 128, K mult of 32.
// causal: 0 none; 1 skip blocks n0>m0+127; 2 truncate K to m0+128
__global__ void __launch_bounds__(256)
hgemm_kernel(const __nv_bfloat16* __restrict__ Ah, const __nv_bfloat16* __restrict__ Al,
             const __nv_bfloat16* __restrict__ Bh, const __nv_bfloat16* __restrict__ Bl,
             float* __restrict__ C,
             int N, int K, int lda, int ldb, int ldc,
             long long sA, long long sB, long long sC,
             const float* __restrict__ bias, int act, int causal) {
    int m0 = blockIdx.y * 128, n0 = blockIdx.x * 128;
    if (causal == 1 && n0 > m0 + 127) return;
    int Keff = (causal == 2) ? min(K, m0 + 128) : K;

    int bz = blockIdx.z;
    Ah += (long long)bz * sA;  Al += (long long)bz * sA;
    Bh += (long long)bz * sB;  Bl += (long long)bz * sB;
    C  += (long long)bz * sC;

    __shared__ __align__(128) __nv_bfloat16 As[2][128 * 32];
    __shared__ __align__(128) __nv_bfloat16 Bs[2][128 * 32];
    uint32_t sa0 = smem_u32(As), sb0 = smem_u32(Bs);

    int tid = threadIdx.x, wid = tid >> 5, lane = tid & 31;
    int wm = (wid & 3) * 32, wn = (wid >> 2) * 64;

    float acc[2][8][4];
#pragma unroll
    for (int i = 0; i < 2; i++)
#pragma unroll
        for (int j = 0; j < 8; j++)
#pragma unroll
            for (int v = 0; v < 4; v++) acc[i][j][v] = 0.f;

    int KC = Keff / 32;
    int T  = 3 * KC;

    // ---- tile loader ----
    auto load_tile = [&](int s, int t) {
        int phase = t / KC;
        int k0 = (t - phase * KC) * 32;
        const __nv_bfloat16* Ap = (phase == 2) ? Al : Ah;
        const __nv_bfloat16* Bp = (phase == 1) ? Bl : Bh;
        uint32_t sa = sa0 + s * 8192, sb = sb0 + s * 8192;
#pragma unroll
        for (int j = 0; j < 2; j++) {
            int u = tid + 256 * j;
            int row = u >> 2, ch = u & 3;
            cpasync16(sa + sw_off(row, ch), Ap + (long long)(m0 + row) * lda + k0 + ch * 8);
        }
#pragma unroll
        for (int j = 0; j < 2; j++) {
            int u = tid + 256 * j;
            int row = u >> 2, ch = u & 3;
            cpasync16(sb + sw_off(row, ch), Bp + (long long)(n0 + row) * ldb + k0 + ch * 8);
        }
        CP_COMMIT();
    };

    load_tile(0, 0);

    for (int t = 0; t < T; t++) {
        int s = t & 1;
        if (t + 1 < T) { load_tile(1 - s, t + 1); CP_WAIT1(); }
        else          { CP_WAIT0(); }
        __syncthreads();

        uint32_t sa = sa0 + s * 8192, sb = sb0 + s * 8192;
#pragma unroll
        for (int kk = 0; kk < 2; kk++) {
            uint32_t afr[2][4];
#pragma unroll
            for (int i = 0; i < 2; i++) {
                int row = wm + i * 16 + (lane & 15);
                int cb = kk * 2 + (lane >> 4);
                ldsm4(afr[i], sa + sw_off(row, cb));
            }
            uint32_t bfr[8][2];
#pragma unroll
            for (int jj = 0; jj < 4; jj++) {
                int row = wn + jj * 16 + (lane & 15);
                int cb = kk * 2 + (lane >> 4);
                uint32_t m[4];
                ldsm4(m, sb + sw_off(row, cb));
                bfr[jj * 2][0] = m[0]; bfr[jj * 2][1] = m[2];
                bfr[jj * 2 + 1][0] = m[1]; bfr[jj * 2 + 1][1] = m[3];
            }
#pragma unroll
            for (int i = 0; i < 2; i++)
#pragma unroll
                for (int j = 0; j < 8; j++)
                    mma16816(acc[i][j], afr[i], bfr[j]);
        }
        __syncthreads();
    }

    // ---- epilogue ----
#pragma unroll
    for (int i = 0; i < 2; i++) {
#pragma unroll
        for (int j = 0; j < 8; j++) {
            int r = m0 + wm + i * 16 + (lane >> 2);
            int c = n0 + wn + j * 8 + (lane & 3) * 2;
            float b0 = 0.f, b1 = 0.f;
            if (bias) { b0 = bias[c]; b1 = bias[c + 1]; }
            float v0 = acc[i][j][0] + b0, v1 = acc[i][j][1] + b1;
            float v2 = acc[i][j][2] + b0, v3 = acc[i][j][3] + b1;
            if (act == 1) {
                v0 = (v0 > 20.f) ? v0 : log1pf(__expf(v0));
                v1 = (v1 > 20.f) ? v1 : log1pf(__expf(v1));
                v2 = (v2 > 20.f) ? v2 : log1pf(__expf(v2));
                v3 = (v3 > 20.f) ? v3 : log1pf(__expf(v3));
            }
            *(float2*)(C + (long long)r * ldc + c)       = make_float2(v0, v1);
            *(float2*)(C + (long long)(r + 8) * ldc + c) = make_float2(v2, v3);
        }
    }
}

// ---------------- fp32 -> bf16 hi/lo split (straight) ----------------
__global__ void split_kernel(const float* __restrict__ src, __nv_bfloat16* __restrict__ hi,
                             __nv_bfloat16* __restrict__ lo, int rows, int cols, int lds) {
    long long idx = (long long)blockIdx.x * blockDim.x + threadIdx.x;
    if (idx >= (long long)rows * cols) return;
    int r = (int)(idx / cols), c = (int)(idx - (long long)r * cols);
    float f = src[(long long)r * lds + c];
    __nv_bfloat16 h = __float2bfloat16(f);
    __nv_bfloat16 l = __float2bfloat16(f - __bfloat162float(h));
    hi[idx] = h; lo[idx] = l;
}

// ---------------- fp32 [K,N] -> bf16 hi/lo transposed [Npad,K] ----------------
__global__ void splitT_kernel(const float* __restrict__ src, __nv_bfloat16* __restrict__ hi,
                              __nv_bfloat16* __restrict__ lo, int K, int N, int lds, int Npad) {
    __shared__ float t[32][33];
    int k0 = blockIdx.x * 32, n0 = blockIdx.y * 32;
    int tx = threadIdx.x & 31, ty = threadIdx.x >> 5;
#pragma unroll
    for (int r = 0; r < 4; r++) {
        int k = k0 + ty + 8 * r;
        int n = n0 + tx;
        t[ty + 8 * r][tx] = (n < N) ? src[(long long)k * lds + n] : 0.f;
    }
    __syncthreads();
#pragma unroll
    for (int r = 0; r < 4; r++) {
        int n = n0 + ty + 8 * r;
        int k = k0 + tx;
        if (n < Npad) {
            float f = t[tx][ty + 8 * r];
            __nv_bfloat16 h = __float2bfloat16(f);
            __nv_bfloat16 l = __float2bfloat16(f - __bfloat162float(h));
            hi[(long long)n * K + k] = h;
            lo[(long long)n * K + k] = l;
        }
    }
}

// ---------------- embed gather ----------------
__global__ void embed_kernel(const int* __restrict__ tokens, const float* __restrict__ ew,
                             float* __restrict__ out) {
    int row = blockIdx.x;
    int tok = tokens[row];
    const float4* src = (const float4*)(ew + (long long)tok * DD);
    float4* dst = (float4*)(out + (long long)row * DD);
    dst[threadIdx.x] = src[threadIdx.x];
}

// ---------------- causal depthwise conv + bias + SiLU ----------------
__global__ void conv_silu_kernel(const float* __restrict__ xz, const float* __restrict__ cw,
                                 const float* __restrict__ cb, float* __restrict__ out) {
    int idx = blockIdx.x * blockDim.x + threadIdx.x;
    if (idx >= RTOT * EDIM) return;
    int e = idx % EDIM;
    int r = idx / EDIM;
    int l = r % LL;
    int b = r / LL;
    float acc = cb[e];
#pragma unroll
    for (int t = 0; t < DCV; t++) {
        int ll = l - (DCV - 1) + t;
        if (ll >= 0)
            acc += cw[e * DCV + t] * xz[(long long)(b * LL + ll) * (2 * EDIM) + e];
    }
    out[idx] = acc / (1.f + __expf(-acc));
}

// ---------------- selective scan ----------------
__global__ void scan_kernel(const float* __restrict__ dbl, const float* __restrict__ delta,
                            const float* __restrict__ xm, const float* __restrict__ xz,
                            const float* __restrict__ A_log, const float* __restrict__ Dp,
                            float* __restrict__ y) {
    int b = blockIdx.y;
    int ed = blockIdx.x * blockDim.x + threadIdx.x;
    float Av[NS];
#pragma unroll
    for (int n = 0; n < NS; n++) Av[n] = -__expf(A_log[ed * NS + n]);
    float h[NS];
#pragma unroll
    for (int n = 0; n < NS; n++) h[n] = 0.f;
    float dp = Dp[ed];
    __shared__ float sBC[32][32];
    for (int l0 = 0; l0 < LL; l0 += 32) {
        __syncthreads();
        for (int u = threadIdx.x; u < 32 * 32; u += blockDim.x) {
            int i = u >> 5, j = u & 31;
            sBC[i][j] = dbl[(long long)(b * LL + l0 + i) * XW + DTR + j];
        }
        __syncthreads();
        for (int i = 0; i < 32; i++) {
            long long row = (long long)b * LL + l0 + i;
            float dlt = delta[row * EDIM + ed];
            float xmv = xm[row * EDIM + ed];
            float zv  = xz[row * (2 * EDIM) + EDIM + ed];
            float dx = dlt * xmv;
            float acc = 0.f;
#pragma unroll
            for (int n = 0; n < NS; n++) {
                float dA = __expf(dlt * Av[n]);
                h[n] = dA * h[n] + dx * sBC[i][n];
                acc += h[n] * sBC[i][NS + n];
            }
            float yv = acc + xmv * dp;
            yv *= zv / (1.f + __expf(-zv));
            y[row * EDIM + ed] = yv;
        }
    }
}

// ---------------- layernorm over D=1024 ----------------
__global__ void layernorm_kernel(const float* __restrict__ x, const float* __restrict__ w,
                                 const float* __restrict__ b, float* __restrict__ out) {
    int row = blockIdx.x;
    int tid = threadIdx.x;
    const float4 v = ((const float4*)(x + (long long)row * DD))[tid];
    float s  = v.x + v.y + v.z + v.w;
    float sq = v.x * v.x + v.y * v.y + v.z * v.z + v.w * v.w;
    __shared__ float ss[256], s2[256];
    ss[tid] = s; s2[tid] = sq;
    __syncthreads();
    for (int st = 128; st > 0; st >>= 1) {
        if (tid < st) { ss[tid] += ss[tid + st]; s2[tid] += s2[tid + st]; }
        __syncthreads();
    }
    float mean = ss[0] * (1.f / DD);
    float var  = s2[0] * (1.f / DD) - mean * mean;
    float inv  = rsqrtf(var + 1e-5f);
    float4 wv = ((const float4*)w)[tid];
    float4 bv = ((const float4*)b)[tid];
    float4 o;
    o.x = (v.x - mean) * inv * wv.x + bv.x;
    o.y = (v.y - mean) * inv * wv.y + bv.y;
    o.z = (v.z - mean) * inv * wv.z + bv.z;
    o.w = (v.w - mean) * inv * wv.w + bv.w;
    ((float4*)(out + (long long)row * DD))[tid] = o;
}

// ---------------- causal softmax ----------------
__global__ void softmax_causal_kernel(float* __restrict__ s) {
    int row = blockIdx.x;
    int q = row % LL;
    int tid = threadIdx.x;
    float* sr = s + (long long)row * LL;
    const float scale = 0.03125f;
    __shared__ float sh[256];
    float mx = -1e30f;
    for (int k = tid; k <= q; k += 256) mx = fmaxf(mx, sr[k] * scale);
    sh[tid] = mx; __syncthreads();
    for (int st = 128; st > 0; st >>= 1) {
        if (tid < st) sh[tid] = fmaxf(sh[tid], sh[tid + st]);
        __syncthreads();
    }
    mx = sh[0];
    __syncthreads();
    float sum = 0.f;
    for (int k = tid; k <= q; k += 256) {
        float e = __expf(sr[k] * scale - mx);
        sr[k] = e;
        sum += e;
    }
    sh[tid] = sum; __syncthreads();
    for (int st = 128; st > 0; st >>= 1) {
        if (tid < st) sh[tid] += sh[tid + st];
        __syncthreads();
    }
    float inv = 1.f / sh[0];
    for (int k = tid; k < LL; k += 256) sr[k] = (k <= q) ? sr[k] * inv : 0.f;
}

// ---------------- launch ----------------
static inline int cdiv(long long a, int b) { return (int)((a + b - 1) / b); }

extern "C" void kernel_launch(void* const* d_in, const int* in_sizes, int n_in,
                              void* d_out, int out_size) {
    const int*   tokens     = (const int*)  d_in[0];
    const float* embed_w    = (const float*)d_in[1];
    const float* in_proj_w  = (const float*)d_in[2];
    const float* conv_w     = (const float*)d_in[3];
    const float* conv_b     = (const float*)d_in[4];
    const float* x_proj_w   = (const float*)d_in[5];
    const float* dt_proj_w  = (const float*)d_in[6];
    const float* dt_proj_b  = (const float*)d_in[7];
    const float* A_log      = (const float*)d_in[8];
    const float* D_p        = (const float*)d_in[9];
    const float* out_proj_w = (const float*)d_in[10];
    const float* ln0_w      = (const float*)d_in[11];
    const float* ln0_b      = (const float*)d_in[12];
    const float* ln1_w      = (const float*)d_in[13];
    const float* ln1_b      = (const float*)d_in[14];
    const float* c_attn_w   = (const float*)d_in[15];
    const float* c_attn_b   = (const float*)d_in[16];
    const float* head_w     = (const float*)d_in[17];
    const float* head_b     = (const float*)d_in[18];
    float* out = (float*)d_out;

    float *px, *pxz, *pxm, *pdbl, *pdelta, *py, *pm0, *pln0, *pqkv, *pscores, *pattn, *pln1;
    cudaGetSymbolAddress((void**)&px,      g_x);
    cudaGetSymbolAddress((void**)&pxz,     g_xz);
    cudaGetSymbolAddress((void**)&pxm,     g_xm);
    cudaGetSymbolAddress((void**)&pdbl,    g_dbl);
    cudaGetSymbolAddress((void**)&pdelta,  g_delta);
    cudaGetSymbolAddress((void**)&py,      g_y);
    cudaGetSymbolAddress((void**)&pm0,     g_m0);
    cudaGetSymbolAddress((void**)&pln0,    g_ln0);
    cudaGetSymbolAddress((void**)&pqkv,    g_qkv);
    cudaGetSymbolAddress((void**)&pscores, g_scores);
    cudaGetSymbolAddress((void**)&pattn,   g_attn);
    cudaGetSymbolAddress((void**)&pln1,    g_ln1);

    __nv_bfloat16 *xa_h,*xa_l,*xm_h,*xm_l,*da_h,*da_l,*yb_h,*yb_l,*l0_h,*l0_l,*qk_h,*qk_l,*pb_h,*pb_l,*l1_h,*l1_l;
    __nv_bfloat16 *wi_h,*wi_l,*wx_h,*wx_l,*wd_h,*wd_l,*wo_h,*wo_l,*wc_h,*wc_l,*vt_h,*vt_l,*wh_h,*wh_l;
    cudaGetSymbolAddress((void**)&xa_h, g_xa_h);  cudaGetSymbolAddress((void**)&xa_l, g_xa_l);
    cudaGetSymbolAddress((void**)&xm_h, g_xmb_h); cudaGetSymbolAddress((void**)&xm_l, g_xmb_l);
    cudaGetSymbolAddress((void**)&da_h, g_da_h);  cudaGetSymbolAddress((void**)&da_l, g_da_l);
    cudaGetSymbolAddress((void**)&yb_h, g_yb_h);  cudaGetSymbolAddress((void**)&yb_l, g_yb_l);
    cudaGetSymbolAddress((void**)&l0_h, g_l0_h);  cudaGetSymbolAddress((void**)&l0_l, g_l0_l);
    cudaGetSymbolAddress((void**)&qk_h, g_qk_h);  cudaGetSymbolAddress((void**)&qk_l, g_qk_l);
    cudaGetSymbolAddress((void**)&pb_h, g_pb_h);  cudaGetSymbolAddress((void**)&pb_l, g_pb_l);
    cudaGetSymbolAddress((void**)&l1_h, g_l1_h);  cudaGetSymbolAddress((void**)&l1_l, g_l1_l);
    cudaGetSymbolAddress((void**)&wi_h, g_wi_h);  cudaGetSymbolAddress((void**)&wi_l, g_wi_l);
    cudaGetSymbolAddress((void**)&wx_h, g_wx_h);  cudaGetSymbolAddress((void**)&wx_l, g_wx_l);
    cudaGetSymbolAddress((void**)&wd_h, g_wd_h);  cudaGetSymbolAddress((void**)&wd_l, g_wd_l);
    cudaGetSymbolAddress((void**)&wo_h, g_wo_h);  cudaGetSymbolAddress((void**)&wo_l, g_wo_l);
    cudaGetSymbolAddress((void**)&wc_h, g_wc_h);  cudaGetSymbolAddress((void**)&wc_l, g_wc_l);
    cudaGetSymbolAddress((void**)&vt_h, g_vt_h);  cudaGetSymbolAddress((void**)&vt_l, g_vt_l);
    cudaGetSymbolAddress((void**)&wh_h, g_wh_h);  cudaGetSymbolAddress((void**)&wh_l, g_wh_l);

    // 1) embed + splits
    embed_kernel<<<RTOT, 256>>>(tokens, embed_w, px);
    split_kernel<<<cdiv((long long)RTOT*DD,256),256>>>(px, xa_h, xa_l, RTOT, DD, DD);
    splitT_kernel<<<dim3(DD/32, 2*EDIM/32), 256>>>(in_proj_w, wi_h, wi_l, DD, 2*EDIM, 2*EDIM, 2*EDIM);

    // 2) in_proj -> g_xz [2048, 4096]
    hgemm_kernel<<<dim3(2*EDIM/128, RTOT/128), 256>>>(
        xa_h, xa_l, wi_h, wi_l, pxz, 2*EDIM, DD, DD, DD, 2*EDIM, 0, 0, 0, nullptr, 0, 0);

    // 3) conv + silu -> g_xm
    conv_silu_kernel<<<cdiv((long long)RTOT*EDIM,256), 256>>>(pxz, conv_w, conv_b, pxm);
    split_kernel<<<cdiv((long long)RTOT*EDIM,256),256>>>(pxm, xm_h, xm_l, RTOT, EDIM, EDIM);
    splitT_kernel<<<dim3(EDIM/32, XW/32), 256>>>(x_proj_w, wx_h, wx_l, EDIM, DTR+2*NS, DTR+2*NS, XW);

    // 4) x_proj -> g_dbl [2048, 128] (padded)
    hgemm_kernel<<<dim3(XW/128, RTOT/128), 256>>>(
        xm_h, xm_l, wx_h, wx_l, pdbl, XW, EDIM, EDIM, EDIM, XW, 0, 0, 0, nullptr, 0, 0);

    // 5) dt_proj (+bias, softplus) -> g_delta
    split_kernel<<<cdiv((long long)RTOT*DTR,256),256>>>(pdbl, da_h, da_l, RTOT, DTR, XW);
    splitT_kernel<<<dim3(DTR/32, EDIM/32), 256>>>(dt_proj_w, wd_h, wd_l, DTR, EDIM, EDIM, EDIM);
    hgemm_kernel<<<dim3(EDIM/128, RTOT/128), 256>>>(
        da_h, da_l, wd_h, wd_l, pdelta, EDIM, DTR, DTR, DTR, EDIM, 0, 0, 0, dt_proj_b, 1, 0);

    // 6) scan -> g_y
    scan_kernel<<<dim3(EDIM/256, BB), 256>>>(pdbl, pdelta, pxm, pxz, A_log, D_p, py);
    split_kernel<<<cdiv((long long)RTOT*EDIM,256),256>>>(py, yb_h, yb_l, RTOT, EDIM, EDIM);
    splitT_kernel<<<dim3(EDIM/32, DD/32), 256>>>(out_proj_w, wo_h, wo_l, EDIM, DD, DD, DD);

    // 7) out_proj -> g_m0
    hgemm_kernel<<<dim3(DD/128, RTOT/128), 256>>>(
        yb_h, yb_l, wo_h, wo_l, pm0, DD, EDIM, EDIM, EDIM, DD, 0, 0, 0, nullptr, 0, 0);

    // 8) layernorm 0
    layernorm_kernel<<<RTOT, 256>>>(pm0, ln0_w, ln0_b, pln0);
    split_kernel<<<cdiv((long long)RTOT*DD,256),256>>>(pln0, l0_h, l0_l, RTOT, DD, DD);
    splitT_kernel<<<dim3(DD/32, 3*DD/32), 256>>>(c_attn_w, wc_h, wc_l, DD, 3*DD, 3*DD, 3*DD);

    // 9) c_attn (+bias) -> g_qkv
    hgemm_kernel<<<dim3(3*DD/128, RTOT/128), 256>>>(
        l0_h, l0_l, wc_h, wc_l, pqkv, 3*DD, DD, DD, DD, 3*DD, 0, 0, 0, c_attn_b, 0, 0);

    // 10) conversions for attention
    split_kernel<<<cdiv((long long)RTOT*3*DD,256),256>>>(pqkv, qk_h, qk_l, RTOT, 3*DD, 3*DD);
    for (int b = 0; b < BB; b++)
        splitT_kernel<<<dim3(LL/32, DD/32), 256>>>(pqkv + (long long)b*LL*3*DD + 2*DD,
                                                   vt_h + (long long)b*DD*LL,
                                                   vt_l + (long long)b*DD*LL,
                                                   LL, DD, 3*DD, DD);

    // 11) scores = Q @ K^T (causal skip of upper blocks)
    hgemm_kernel<<<dim3(LL/128, LL/128, BB), 256>>>(
        qk_h, qk_l, qk_h + DD, qk_l + DD, pscores, LL, DD, 3*DD, 3*DD, LL,
        (long long)LL*3*DD, (long long)LL*3*DD, (long long)LL*LL, nullptr, 0, 1);

    // 12) softmax
    softmax_causal_kernel<<<BB*LL, 256>>>(pscores);
    split_kernel<<<cdiv((long long)BB*LL*LL,256),256>>>(pscores, pb_h, pb_l, BB*LL, LL, LL);

    // 13) attn @ V (K truncated to m0+128)
    hgemm_kernel<<<dim3(DD/128, LL/128, BB), 256>>>(
        pb_h, pb_l, vt_h, vt_l, pattn, DD, LL, LL, LL, DD,
        (long long)LL*LL, (long long)DD*LL, (long long)LL*DD, nullptr, 0, 2);

    // 14) layernorm 1
    layernorm_kernel<<<RTOT, 256>>>(pattn, ln1_w, ln1_b, pln1);
    split_kernel<<<cdiv((long long)RTOT*DD,256),256>>>(pln1, l1_h, l1_l, RTOT, DD, DD);
    splitT_kernel<<<dim3(DD/32, VV/32), 256>>>(head_w, wh_h, wh_l, DD, VV, VV, VV);

    // 15) head (+bias) -> out
    hgemm_kernel<<<dim3(VV/128, RTOT/128), 256>>>(
        l1_h, l1_l, wh_h, wh_l, out, VV, DD, DD, DD, VV, 0, 0, 0, head_b, 0, 0);
}

// round 6
// speedup vs baseline: 2.0516x; 1.0588x over previous
#include <cuda_runtime.h>
#include <cuda_bf16.h>
#include <math.h>
#include <stdint.h>

// ---------------- problem constants ----------------
#define BB   2
#define LL   1024
#define DD   1024
#define EDIM 2048
#define NS   16
#define DCV  4
#define DTR  64
#define VV   32000
#define RTOT (BB*LL)
#define XW   128        // x_proj output width padded 96 -> 128

// ---------------- fp32 scratch ----------------
__device__ float g_xz[RTOT*2*EDIM];
__device__ float g_xm[RTOT*EDIM];
__device__ float g_dbl[RTOT*XW];        // [delta(64) | B(16) | C(16) | pad(32)]
__device__ float g_delta[RTOT*EDIM];
__device__ float g_m0[RTOT*DD];
__device__ float g_scores[BB*LL*LL];
__device__ float g_attn[RTOT*DD];

// ---------------- bf16 hi/lo split buffers ----------------
#define AL __align__(256)
__device__ AL __nv_bfloat16 g_xa_h[RTOT*DD],   g_xa_l[RTOT*DD];      // embed out
__device__ AL __nv_bfloat16 g_xmb_h[RTOT*EDIM],g_xmb_l[RTOT*EDIM];   // conv out
__device__ AL __nv_bfloat16 g_da_h[RTOT*DTR],  g_da_l[RTOT*DTR];     // delta-pre (x_proj cols 0..63)
__device__ AL __nv_bfloat16 g_yb_h[RTOT*EDIM], g_yb_l[RTOT*EDIM];    // scan out
__device__ AL __nv_bfloat16 g_l0_h[RTOT*DD],   g_l0_l[RTOT*DD];      // ln0 out
__device__ AL __nv_bfloat16 g_qk_h[RTOT*3*DD], g_qk_l[RTOT*3*DD];    // c_attn out
__device__ AL __nv_bfloat16 g_pb_h[BB*LL*LL],  g_pb_l[BB*LL*LL];     // softmax out
__device__ AL __nv_bfloat16 g_l1_h[RTOT*DD],   g_l1_l[RTOT*DD];      // ln1 out
// weights transposed to [N, K]
__device__ AL __nv_bfloat16 g_wi_h[2*EDIM*DD], g_wi_l[2*EDIM*DD];
__device__ AL __nv_bfloat16 g_wx_h[XW*EDIM],   g_wx_l[XW*EDIM];
__device__ AL __nv_bfloat16 g_wd_h[EDIM*DTR],  g_wd_l[EDIM*DTR];
__device__ AL __nv_bfloat16 g_wo_h[DD*EDIM],   g_wo_l[DD*EDIM];
__device__ AL __nv_bfloat16 g_wc_h[3*DD*DD],   g_wc_l[3*DD*DD];
__device__ AL __nv_bfloat16 g_vt_h[BB*DD*LL],  g_vt_l[BB*DD*LL];
__device__ AL __nv_bfloat16 g_wh_h[VV*DD],     g_wh_l[VV*DD];

// ---------------- mma helpers ----------------
__device__ __forceinline__ uint32_t smem_u32(const void* p) {
    uint32_t a;
    asm("{ .reg .u64 t; cvta.to.shared.u64 t, %1; cvt.u32.u64 %0, t; }" : "=r"(a) : "l"(p));
    return a;
}
__device__ __forceinline__ void ldsm4(uint32_t* r, uint32_t addr) {
    asm volatile("ldmatrix.sync.aligned.m8n8.x4.shared.b16 {%0,%1,%2,%3}, [%4];"
        : "=r"(r[0]), "=r"(r[1]), "=r"(r[2]), "=r"(r[3]) : "r"(addr));
}
__device__ __forceinline__ void mma16816(float* c, const uint32_t* a, const uint32_t* b) {
    asm volatile("mma.sync.aligned.m16n8k16.row.col.f32.bf16.bf16.f32 "
        "{%0,%1,%2,%3}, {%4,%5,%6,%7}, {%8,%9}, {%0,%1,%2,%3};"
        : "+f"(c[0]), "+f"(c[1]), "+f"(c[2]), "+f"(c[3])
        : "r"(a[0]), "r"(a[1]), "r"(a[2]), "r"(a[3]), "r"(b[0]), "r"(b[1]));
}
__device__ __forceinline__ void cpasync16(uint32_t dst, const void* src) {
    asm volatile("cp.async.cg.shared.global [%0], [%1], 16;" :: "r"(dst), "l"(src));
}
#define CP_COMMIT() asm volatile("cp.async.commit_group;" ::: "memory")
#define CP_WAIT2()  asm volatile("cp.async.wait_group 2;" ::: "memory")

// smem tile: 128 rows x 32 bf16 (64B/row), swizzle: chunk ^= (row>>1)&3
__device__ __forceinline__ uint32_t sw_off(int row, int chunk) {
    return (uint32_t)(row * 64 + ((chunk ^ ((row >> 1) & 3)) << 4));
}

#define STAGES      3
#define TILE_BYTES  8192
#define STAGE_BYTES (4*TILE_BYTES)   // Ah|Al|Bh|Bl
#define GEMM_SMEM   (STAGES*STAGE_BYTES)  // 98304

// ---------------- fused-precision GEMM ----------------
// C[M,N] = (Ah+Al)(Bh+Bl)^T via Ah·Bh + Ah·Bl + Al·Bh, all staged once per k-tile.
// A row-major [M,K] (lda), B row-major [N,K] (ldb). M,N mult 128, K mult 32.
// causal: 0 none; 1 skip n0>m0+127; 2 truncate K to m0+128.
// Outputs: if C: fp32; if Oh: bf16 hi/lo (cols < splitCols), stride ldo.
__global__ void __launch_bounds__(512)
hgemm2_kernel(const __nv_bfloat16* __restrict__ Ah, const __nv_bfloat16* __restrict__ Al,
              const __nv_bfloat16* __restrict__ Bh, const __nv_bfloat16* __restrict__ Bl,
              float* __restrict__ C, __nv_bfloat16* __restrict__ Oh, __nv_bfloat16* __restrict__ Ol,
              int N, int K, int lda, int ldb, int ldc, int ldo, int splitCols,
              long long sA, long long sB, long long sC, long long sO,
              const float* __restrict__ bias, int act, int causal) {
    extern __shared__ char smem[];
    int m0 = blockIdx.y * 128, n0 = blockIdx.x * 128;
    if (causal == 1 && n0 > m0 + 127) return;
    int Keff = (causal == 2) ? min(K, m0 + 128) : K;

    int bz = blockIdx.z;
    Ah += (long long)bz * sA;  Al += (long long)bz * sA;
    Bh += (long long)bz * sB;  Bl += (long long)bz * sB;
    if (C)  C  += (long long)bz * sC;
    if (Oh) { Oh += (long long)bz * sO; Ol += (long long)bz * sO; }

    uint32_t sbase = smem_u32(smem);
    int tid = threadIdx.x, wid = tid >> 5, lane = tid & 31;
    int wm = (wid & 3) * 32, wn = (wid >> 2) * 32;

    float acc[2][4][4];
#pragma unroll
    for (int i = 0; i < 2; i++)
#pragma unroll
        for (int j = 0; j < 4; j++)
#pragma unroll
            for (int v = 0; v < 4; v++) acc[i][j][v] = 0.f;

    // loader: 512 threads, one 16B chunk per tile each
    int lrow = tid >> 2, lch = tid & 3;
    uint32_t soff = sw_off(lrow, lch);
    const char* gAh = (const char*)(Ah + (long long)(m0 + lrow) * lda + lch * 8);
    const char* gAl = (const char*)(Al + (long long)(m0 + lrow) * lda + lch * 8);
    const char* gBh = (const char*)(Bh + (long long)(n0 + lrow) * ldb + lch * 8);
    const char* gBl = (const char*)(Bl + (long long)(n0 + lrow) * ldb + lch * 8);

    int KC = Keff / 32;

    auto load_stage = [&](int t) {
        uint32_t sb = sbase + (t % STAGES) * STAGE_BYTES;
        long long koff = (long long)t * 64;  // 32 bf16 = 64 bytes
        cpasync16(sb + soff,                  gAh + koff);
        cpasync16(sb + TILE_BYTES + soff,     gAl + koff);
        cpasync16(sb + 2*TILE_BYTES + soff,   gBh + koff);
        cpasync16(sb + 3*TILE_BYTES + soff,   gBl + koff);
    };

    // prologue: stages for t=0,1
    load_stage(0); CP_COMMIT();
    if (KC > 1) load_stage(1);
    CP_COMMIT();

    for (int t = 0; t < KC; t++) {
        if (t + 2 < KC) load_stage(t + 2);
        CP_COMMIT();
        CP_WAIT2();
        __syncthreads();

        uint32_t sb = sbase + (t % STAGES) * STAGE_BYTES;
#pragma unroll
        for (int kk = 0; kk < 2; kk++) {
            uint32_t ah[2][4], al[2][4];
#pragma unroll
            for (int i = 0; i < 2; i++) {
                int row = wm + i * 16 + (lane & 15);
                int cb = kk * 2 + (lane >> 4);
                uint32_t o = sw_off(row, cb);
                ldsm4(ah[i], sb + o);
                ldsm4(al[i], sb + TILE_BYTES + o);
            }
            uint32_t bh[4][2], bl[4][2];
#pragma unroll
            for (int jj = 0; jj < 2; jj++) {
                int row = wn + jj * 16 + (lane & 15);
                int cb = kk * 2 + (lane >> 4);
                uint32_t o = sw_off(row, cb);
                uint32_t m[4];
                ldsm4(m, sb + 2*TILE_BYTES + o);
                bh[jj*2][0] = m[0]; bh[jj*2][1] = m[2];
                bh[jj*2+1][0] = m[1]; bh[jj*2+1][1] = m[3];
                ldsm4(m, sb + 3*TILE_BYTES + o);
                bl[jj*2][0] = m[0]; bl[jj*2][1] = m[2];
                bl[jj*2+1][0] = m[1]; bl[jj*2+1][1] = m[3];
            }
#pragma unroll
            for (int i = 0; i < 2; i++)
#pragma unroll
                for (int j = 0; j < 4; j++) {
                    mma16816(acc[i][j], ah[i], bh[j]);
                    mma16816(acc[i][j], ah[i], bl[j]);
                    mma16816(acc[i][j], al[i], bh[j]);
                }
        }
        __syncthreads();
    }

    // ---- epilogue ----
#pragma unroll
    for (int i = 0; i < 2; i++) {
#pragma unroll
        for (int j = 0; j < 4; j++) {
            int r = m0 + wm + i * 16 + (lane >> 2);
            int c = n0 + wn + j * 8 + (lane & 3) * 2;
            float b0 = 0.f, b1 = 0.f;
            if (bias) { b0 = bias[c]; b1 = bias[c + 1]; }
            float v0 = acc[i][j][0] + b0, v1 = acc[i][j][1] + b1;
            float v2 = acc[i][j][2] + b0, v3 = acc[i][j][3] + b1;
            if (act == 1) {
                v0 = (v0 > 20.f) ? v0 : log1pf(__expf(v0));
                v1 = (v1 > 20.f) ? v1 : log1pf(__expf(v1));
                v2 = (v2 > 20.f) ? v2 : log1pf(__expf(v2));
                v3 = (v3 > 20.f) ? v3 : log1pf(__expf(v3));
            }
            if (C) {
                *(float2*)(C + (long long)r * ldc + c)       = make_float2(v0, v1);
                *(float2*)(C + (long long)(r + 8) * ldc + c) = make_float2(v2, v3);
            }
            if (Oh && c < splitCols) {
                __nv_bfloat16 h0 = __float2bfloat16(v0);
                __nv_bfloat16 h1 = __float2bfloat16(v1);
                __nv_bfloat16 h2 = __float2bfloat16(v2);
                __nv_bfloat16 h3 = __float2bfloat16(v3);
                long long o0 = (long long)r * ldo + c, o1 = (long long)(r + 8) * ldo + c;
                Oh[o0] = h0; Oh[o0 + 1] = h1;
                Oh[o1] = h2; Oh[o1 + 1] = h3;
                Ol[o0]     = __float2bfloat16(v0 - __bfloat162float(h0));
                Ol[o0 + 1] = __float2bfloat16(v1 - __bfloat162float(h1));
                Ol[o1]     = __float2bfloat16(v2 - __bfloat162float(h2));
                Ol[o1 + 1] = __float2bfloat16(v3 - __bfloat162float(h3));
            }
        }
    }
}

// ---------------- fp32 [K,N] -> bf16 hi/lo transposed [Npad,K] ----------------
__global__ void splitT_kernel(const float* __restrict__ src, __nv_bfloat16* __restrict__ hi,
                              __nv_bfloat16* __restrict__ lo, int K, int N, int lds, int Npad) {
    __shared__ float t[32][33];
    int k0 = blockIdx.x * 32, n0 = blockIdx.y * 32;
    int tx = threadIdx.x & 31, ty = threadIdx.x >> 5;
#pragma unroll
    for (int r = 0; r < 4; r++) {
        int k = k0 + ty + 8 * r;
        int n = n0 + tx;
        t[ty + 8 * r][tx] = (n < N) ? src[(long long)k * lds + n] : 0.f;
    }
    __syncthreads();
#pragma unroll
    for (int r = 0; r < 4; r++) {
        int n = n0 + ty + 8 * r;
        int k = k0 + tx;
        if (n < Npad) {
            float f = t[tx][ty + 8 * r];
            __nv_bfloat16 h = __float2bfloat16(f);
            __nv_bfloat16 l = __float2bfloat16(f - __bfloat162float(h));
            hi[(long long)n * K + k] = h;
            lo[(long long)n * K + k] = l;
        }
    }
}

// ---------------- bf16 pair transpose (exact): [rows,cols,lds] -> [cols,rows,ldd] ----------------
__global__ void transpose2_bf16(const __nv_bfloat16* __restrict__ srcH,
                                const __nv_bfloat16* __restrict__ srcL,
                                __nv_bfloat16* __restrict__ dstH,
                                __nv_bfloat16* __restrict__ dstL,
                                int rows, int cols, int lds, int ldd,
                                long long sSrc, long long sDst) {
    __shared__ __nv_bfloat16 t[32][33];
    int bz = blockIdx.z;
    srcH += (long long)bz * sSrc; srcL += (long long)bz * sSrc;
    dstH += (long long)bz * sDst; dstL += (long long)bz * sDst;
    int r0 = blockIdx.x * 32, c0 = blockIdx.y * 32;
    int tx = threadIdx.x & 31, ty = threadIdx.x >> 5;
#pragma unroll
    for (int rr = 0; rr < 4; rr++)
        t[ty + 8*rr][tx] = srcH[(long long)(r0 + ty + 8*rr) * lds + c0 + tx];
    __syncthreads();
#pragma unroll
    for (int rr = 0; rr < 4; rr++)
        dstH[(long long)(c0 + ty + 8*rr) * ldd + r0 + tx] = t[tx][ty + 8*rr];
    __syncthreads();
#pragma unroll
    for (int rr = 0; rr < 4; rr++)
        t[ty + 8*rr][tx] = srcL[(long long)(r0 + ty + 8*rr) * lds + c0 + tx];
    __syncthreads();
#pragma unroll
    for (int rr = 0; rr < 4; rr++)
        dstL[(long long)(c0 + ty + 8*rr) * ldd + r0 + tx] = t[tx][ty + 8*rr];
}

// ---------------- embed gather -> bf16 hi/lo ----------------
__global__ void embed_kernel(const int* __restrict__ tokens, const float* __restrict__ ew,
                             __nv_bfloat16* __restrict__ hi, __nv_bfloat16* __restrict__ lo) {
    int row = blockIdx.x;
    int tok = tokens[row];
    float4 v = ((const float4*)(ew + (long long)tok * DD))[threadIdx.x];
    long long base = (long long)row * DD + threadIdx.x * 4;
    float f[4] = {v.x, v.y, v.z, v.w};
#pragma unroll
    for (int u = 0; u < 4; u++) {
        __nv_bfloat16 h = __float2bfloat16(f[u]);
        hi[base + u] = h;
        lo[base + u] = __float2bfloat16(f[u] - __bfloat162float(h));
    }
}

// ---------------- causal depthwise conv + bias + SiLU -> fp32 + hi/lo ----------------
__global__ void conv_silu_kernel(const float* __restrict__ xz, const float* __restrict__ cw,
                                 const float* __restrict__ cb, float* __restrict__ out,
                                 __nv_bfloat16* __restrict__ hi, __nv_bfloat16* __restrict__ lo) {
    int idx = blockIdx.x * blockDim.x + threadIdx.x;
    if (idx >= RTOT * EDIM) return;
    int e = idx % EDIM;
    int r = idx / EDIM;
    int l = r % LL;
    int b = r / LL;
    float acc = cb[e];
#pragma unroll
    for (int t = 0; t < DCV; t++) {
        int ll = l - (DCV - 1) + t;
        if (ll >= 0)
            acc += cw[e * DCV + t] * xz[(long long)(b * LL + ll) * (2 * EDIM) + e];
    }
    float v = acc / (1.f + __expf(-acc));
    out[idx] = v;
    __nv_bfloat16 h = __float2bfloat16(v);
    hi[idx] = h;
    lo[idx] = __float2bfloat16(v - __bfloat162float(h));
}

// ---------------- selective scan -> bf16 hi/lo ----------------
__global__ void scan_kernel(const float* __restrict__ dbl, const float* __restrict__ delta,
                            const float* __restrict__ xm, const float* __restrict__ xz,
                            const float* __restrict__ A_log, const float* __restrict__ Dp,
                            __nv_bfloat16* __restrict__ yh, __nv_bfloat16* __restrict__ yl) {
    int b = blockIdx.y;
    int ed = blockIdx.x * blockDim.x + threadIdx.x;
    float Av[NS];
#pragma unroll
    for (int n = 0; n < NS; n++) Av[n] = -__expf(A_log[ed * NS + n]);
    float h[NS];
#pragma unroll
    for (int n = 0; n < NS; n++) h[n] = 0.f;
    float dp = Dp[ed];
    __shared__ float sBC[32][32];
    for (int l0 = 0; l0 < LL; l0 += 32) {
        __syncthreads();
        for (int u = threadIdx.x; u < 32 * 32; u += blockDim.x) {
            int i = u >> 5, j = u & 31;
            sBC[i][j] = dbl[(long long)(b * LL + l0 + i) * XW + DTR + j];
        }
        __syncthreads();
        for (int i = 0; i < 32; i++) {
            long long row = (long long)b * LL + l0 + i;
            float dlt = delta[row * EDIM + ed];
            float xmv = xm[row * EDIM + ed];
            float zv  = xz[row * (2 * EDIM) + EDIM + ed];
            float dx = dlt * xmv;
            float acc = 0.f;
#pragma unroll
            for (int n = 0; n < NS; n++) {
                float dA = __expf(dlt * Av[n]);
                h[n] = dA * h[n] + dx * sBC[i][n];
                acc += h[n] * sBC[i][NS + n];
            }
            float yv = acc + xmv * dp;
            yv *= zv / (1.f + __expf(-zv));
            __nv_bfloat16 hh = __float2bfloat16(yv);
            yh[row * EDIM + ed] = hh;
            yl[row * EDIM + ed] = __float2bfloat16(yv - __bfloat162float(hh));
        }
    }
}

// ---------------- layernorm over D=1024 -> bf16 hi/lo ----------------
__global__ void layernorm_kernel(const float* __restrict__ x, const float* __restrict__ w,
                                 const float* __restrict__ b,
                                 __nv_bfloat16* __restrict__ oh, __nv_bfloat16* __restrict__ ol) {
    int row = blockIdx.x;
    int tid = threadIdx.x;
    const float4 v = ((const float4*)(x + (long long)row * DD))[tid];
    float s  = v.x + v.y + v.z + v.w;
    float sq = v.x * v.x + v.y * v.y + v.z * v.z + v.w * v.w;
    __shared__ float ss[256], s2[256];
    ss[tid] = s; s2[tid] = sq;
    __syncthreads();
    for (int st = 128; st > 0; st >>= 1) {
        if (tid < st) { ss[tid] += ss[tid + st]; s2[tid] += s2[tid + st]; }
        __syncthreads();
    }
    float mean = ss[0] * (1.f / DD);
    float var  = s2[0] * (1.f / DD) - mean * mean;
    float inv  = rsqrtf(var + 1e-5f);
    float4 wv = ((const float4*)w)[tid];
    float4 bv = ((const float4*)b)[tid];
    float o[4];
    o[0] = (v.x - mean) * inv * wv.x + bv.x;
    o[1] = (v.y - mean) * inv * wv.y + bv.y;
    o[2] = (v.z - mean) * inv * wv.z + bv.z;
    o[3] = (v.w - mean) * inv * wv.w + bv.w;
    long long base = (long long)row * DD + tid * 4;
#pragma unroll
    for (int u = 0; u < 4; u++) {
        __nv_bfloat16 h = __float2bfloat16(o[u]);
        oh[base + u] = h;
        ol[base + u] = __float2bfloat16(o[u] - __bfloat162float(h));
    }
}

// ---------------- causal softmax -> bf16 hi/lo ----------------
__global__ void softmax_causal_kernel(float* __restrict__ s,
                                      __nv_bfloat16* __restrict__ ph, __nv_bfloat16* __restrict__ pl) {
    int row = blockIdx.x;
    int q = row % LL;
    int tid = threadIdx.x;
    float* sr = s + (long long)row * LL;
    const float scale = 0.03125f;
    __shared__ float sh[256];
    float mx = -1e30f;
    for (int k = tid; k <= q; k += 256) mx = fmaxf(mx, sr[k] * scale);
    sh[tid] = mx; __syncthreads();
    for (int st = 128; st > 0; st >>= 1) {
        if (tid < st) sh[tid] = fmaxf(sh[tid], sh[tid + st]);
        __syncthreads();
    }
    mx = sh[0];
    __syncthreads();
    float sum = 0.f;
    for (int k = tid; k <= q; k += 256) {
        float e = __expf(sr[k] * scale - mx);
        sr[k] = e;
        sum += e;
    }
    sh[tid] = sum; __syncthreads();
    for (int st = 128; st > 0; st >>= 1) {
        if (tid < st) sh[tid] += sh[tid + st];
        __syncthreads();
    }
    float inv = 1.f / sh[0];
    long long base = (long long)row * LL;
    for (int k = tid; k < LL; k += 256) {
        float p = (k <= q) ? sr[k] * inv : 0.f;
        __nv_bfloat16 h = __float2bfloat16(p);
        ph[base + k] = h;
        pl[base + k] = __float2bfloat16(p - __bfloat162float(h));
    }
}

// ---------------- launch ----------------
static inline int cdiv(long long a, int b) { return (int)((a + b - 1) / b); }

extern "C" void kernel_launch(void* const* d_in, const int* in_sizes, int n_in,
                              void* d_out, int out_size) {
    const int*   tokens     = (const int*)  d_in[0];
    const float* embed_w    = (const float*)d_in[1];
    const float* in_proj_w  = (const float*)d_in[2];
    const float* conv_w     = (const float*)d_in[3];
    const float* conv_b     = (const float*)d_in[4];
    const float* x_proj_w   = (const float*)d_in[5];
    const float* dt_proj_w  = (const float*)d_in[6];
    const float* dt_proj_b  = (const float*)d_in[7];
    const float* A_log      = (const float*)d_in[8];
    const float* D_p        = (const float*)d_in[9];
    const float* out_proj_w = (const float*)d_in[10];
    const float* ln0_w      = (const float*)d_in[11];
    const float* ln0_b      = (const float*)d_in[12];
    const float* ln1_w      = (const float*)d_in[13];
    const float* ln1_b      = (const float*)d_in[14];
    const float* c_attn_w   = (const float*)d_in[15];
    const float* c_attn_b   = (const float*)d_in[16];
    const float* head_w     = (const float*)d_in[17];
    const float* head_b     = (const float*)d_in[18];
    float* out = (float*)d_out;

    cudaFuncSetAttribute(hgemm2_kernel, cudaFuncAttributeMaxDynamicSharedMemorySize, GEMM_SMEM);

    float *pxz, *pxm, *pdbl, *pdelta, *pm0, *pscores, *pattn;
    cudaGetSymbolAddress((void**)&pxz,     g_xz);
    cudaGetSymbolAddress((void**)&pxm,     g_xm);
    cudaGetSymbolAddress((void**)&pdbl,    g_dbl);
    cudaGetSymbolAddress((void**)&pdelta,  g_delta);
    cudaGetSymbolAddress((void**)&pm0,     g_m0);
    cudaGetSymbolAddress((void**)&pscores, g_scores);
    cudaGetSymbolAddress((void**)&pattn,   g_attn);

    __nv_bfloat16 *xa_h,*xa_l,*xm_h,*xm_l,*da_h,*da_l,*yb_h,*yb_l,*l0_h,*l0_l,*qk_h,*qk_l,*pb_h,*pb_l,*l1_h,*l1_l;
    __nv_bfloat16 *wi_h,*wi_l,*wx_h,*wx_l,*wd_h,*wd_l,*wo_h,*wo_l,*wc_h,*wc_l,*vt_h,*vt_l,*wh_h,*wh_l;
    cudaGetSymbolAddress((void**)&xa_h, g_xa_h);  cudaGetSymbolAddress((void**)&xa_l, g_xa_l);
    cudaGetSymbolAddress((void**)&xm_h, g_xmb_h); cudaGetSymbolAddress((void**)&xm_l, g_xmb_l);
    cudaGetSymbolAddress((void**)&da_h, g_da_h);  cudaGetSymbolAddress((void**)&da_l, g_da_l);
    cudaGetSymbolAddress((void**)&yb_h, g_yb_h);  cudaGetSymbolAddress((void**)&yb_l, g_yb_l);
    cudaGetSymbolAddress((void**)&l0_h, g_l0_h);  cudaGetSymbolAddress((void**)&l0_l, g_l0_l);
    cudaGetSymbolAddress((void**)&qk_h, g_qk_h);  cudaGetSymbolAddress((void**)&qk_l, g_qk_l);
    cudaGetSymbolAddress((void**)&pb_h, g_pb_h);  cudaGetSymbolAddress((void**)&pb_l, g_pb_l);
    cudaGetSymbolAddress((void**)&l1_h, g_l1_h);  cudaGetSymbolAddress((void**)&l1_l, g_l1_l);
    cudaGetSymbolAddress((void**)&wi_h, g_wi_h);  cudaGetSymbolAddress((void**)&wi_l, g_wi_l);
    cudaGetSymbolAddress((void**)&wx_h, g_wx_h);  cudaGetSymbolAddress((void**)&wx_l, g_wx_l);
    cudaGetSymbolAddress((void**)&wd_h, g_wd_h);  cudaGetSymbolAddress((void**)&wd_l, g_wd_l);
    cudaGetSymbolAddress((void**)&wo_h, g_wo_h);  cudaGetSymbolAddress((void**)&wo_l, g_wo_l);
    cudaGetSymbolAddress((void**)&wc_h, g_wc_h);  cudaGetSymbolAddress((void**)&wc_l, g_wc_l);
    cudaGetSymbolAddress((void**)&vt_h, g_vt_h);  cudaGetSymbolAddress((void**)&vt_l, g_vt_l);
    cudaGetSymbolAddress((void**)&wh_h, g_wh_h);  cudaGetSymbolAddress((void**)&wh_l, g_wh_l);

    // 1) embed -> xa hi/lo ; weight transposes
    embed_kernel<<<RTOT, 256>>>(tokens, embed_w, xa_h, xa_l);
    splitT_kernel<<<dim3(DD/32, 2*EDIM/32), 256>>>(in_proj_w, wi_h, wi_l, DD, 2*EDIM, 2*EDIM, 2*EDIM);

    // 2) in_proj -> g_xz fp32 [2048, 4096]
    hgemm2_kernel<<<dim3(2*EDIM/128, RTOT/128), 512, GEMM_SMEM>>>(
        xa_h, xa_l, wi_h, wi_l, pxz, nullptr, nullptr,
        2*EDIM, DD, DD, DD, 2*EDIM, 0, 0, 0, 0, 0, 0, nullptr, 0, 0);

    // 3) conv + silu -> g_xm fp32 + xm hi/lo
    conv_silu_kernel<<<cdiv((long long)RTOT*EDIM,256), 256>>>(pxz, conv_w, conv_b, pxm, xm_h, xm_l);
    splitT_kernel<<<dim3(EDIM/32, XW/32), 256>>>(x_proj_w, wx_h, wx_l, EDIM, DTR+2*NS, DTR+2*NS, XW);

    // 4) x_proj -> g_dbl fp32 [2048,128] + da hi/lo (cols<64)
    hgemm2_kernel<<<dim3(XW/128, RTOT/128), 512, GEMM_SMEM>>>(
        xm_h, xm_l, wx_h, wx_l, pdbl, da_h, da_l,
        XW, EDIM, EDIM, EDIM, XW, DTR, DTR, 0, 0, 0, 0, nullptr, 0, 0);

    // 5) dt_proj (+bias, softplus) -> g_delta fp32
    splitT_kernel<<<dim3(DTR/32, EDIM/32), 256>>>(dt_proj_w, wd_h, wd_l, DTR, EDIM, EDIM, EDIM);
    hgemm2_kernel<<<dim3(EDIM/128, RTOT/128), 512, GEMM_SMEM>>>(
        da_h, da_l, wd_h, wd_l, pdelta, nullptr, nullptr,
        EDIM, DTR, DTR, DTR, EDIM, 0, 0, 0, 0, 0, 0, dt_proj_b, 1, 0);

    // 6) scan -> yb hi/lo
    scan_kernel<<<dim3(EDIM/256, BB), 256>>>(pdbl, pdelta, pxm, pxz, A_log, D_p, yb_h, yb_l);
    splitT_kernel<<<dim3(EDIM/32, DD/32), 256>>>(out_proj_w, wo_h, wo_l, EDIM, DD, DD, DD);

    // 7) out_proj -> g_m0 fp32
    hgemm2_kernel<<<dim3(DD/128, RTOT/128), 512, GEMM_SMEM>>>(
        yb_h, yb_l, wo_h, wo_l, pm0, nullptr, nullptr,
        DD, EDIM, EDIM, EDIM, DD, 0, 0, 0, 0, 0, 0, nullptr, 0, 0);

    // 8) layernorm 0 -> l0 hi/lo
    layernorm_kernel<<<RTOT, 256>>>(pm0, ln0_w, ln0_b, l0_h, l0_l);
    splitT_kernel<<<dim3(DD/32, 3*DD/32), 256>>>(c_attn_w, wc_h, wc_l, DD, 3*DD, 3*DD, 3*DD);

    // 9) c_attn (+bias) -> qk hi/lo only
    hgemm2_kernel<<<dim3(3*DD/128, RTOT/128), 512, GEMM_SMEM>>>(
        l0_h, l0_l, wc_h, wc_l, nullptr, qk_h, qk_l,
        3*DD, DD, DD, DD, 0, 3*DD, 3*DD, 0, 0, 0, 0, c_attn_b, 0, 0);

    // 10) V^T (exact bf16 pair transpose), per batch
    transpose2_bf16<<<dim3(LL/32, DD/32, BB), 256>>>(
        qk_h + 2*DD, qk_l + 2*DD, vt_h, vt_l, LL, DD, 3*DD, LL,
        (long long)LL*3*DD, (long long)DD*LL);

    // 11) scores = Q @ K^T (causal skip), batched
    hgemm2_kernel<<<dim3(LL/128, LL/128, BB), 512, GEMM_SMEM>>>(
        qk_h, qk_l, qk_h + DD, qk_l + DD, pscores, nullptr, nullptr,
        LL, DD, 3*DD, 3*DD, LL, 0, 0,
        (long long)LL*3*DD, (long long)LL*3*DD, (long long)LL*LL, 0, nullptr, 0, 1);

    // 12) softmax -> pb hi/lo
    softmax_causal_kernel<<<BB*LL, 256>>>(pscores, pb_h, pb_l);

    // 13) attn @ V (K truncated), batched -> g_attn fp32
    hgemm2_kernel<<<dim3(DD/128, LL/128, BB), 512, GEMM_SMEM>>>(
        pb_h, pb_l, vt_h, vt_l, pattn, nullptr, nullptr,
        DD, LL, LL, LL, DD, 0, 0,
        (long long)LL*LL, (long long)DD*LL, (long long)LL*DD, 0, nullptr, 0, 2);

    // 14) layernorm 1 -> l1 hi/lo
    layernorm_kernel<<<RTOT, 256>>>(pattn, ln1_w, ln1_b, l1_h, l1_l);
    splitT_kernel<<<dim3(DD/32, VV/32), 256>>>(head_w, wh_h, wh_l, DD, VV, VV, VV);

    // 15) head (+bias) -> out fp32
    hgemm2_kernel<<<dim3(VV/128, RTOT/128), 512, GEMM_SMEM>>>(
        l1_h, l1_l, wh_h, wh_l, out, nullptr, nullptr,
        VV, DD, DD, DD, VV, 0, 0, 0, 0, 0, 0, head_b, 0, 0);
}